// round 12
// baseline (speedup 1.0000x reference)
#include <cuda_runtime.h>
#include <cstdint>

#define NB 64
#define NC 2048
#define NPOS9 729          // 27*27
#define TOTPOS (NB*NPOS9)  // 46656
#define KSEL 819
#define SEL_CAP 512
#define WIN 0.28f

__device__ float g_conv[(size_t)NB * NPOS9 * NC];  // NHWC: [b][p][c]
__device__ float g_t1[TOTPOS];
__device__ float g_t2[TOTPOS];
__device__ float g_t0;

// ---------------------------------------------------------------------------
// Kernel 1: conv (VALID, stride 1) -> NHWC scratch.  fp32 via fma.rn.f32x2.
// ---------------------------------------------------------------------------
#define CONV_XS2_U64 3072
#define CONV_W_U64  (108 * 4 * 16)
#define CONV_SMEM ((CONV_XS2_U64 + CONV_W_U64) * 8)

__global__ void __launch_bounds__(256) conv_kernel(const float* __restrict__ x,
                                                   const float* __restrict__ w)
{
    extern __shared__ unsigned long long smem64[];
    float2* xs2 = (float2*)smem64;
    float2* ws2 = (float2*)(smem64 + CONV_XS2_U64);
    const unsigned long long* xsu = smem64;
    const unsigned long long* wsu = smem64 + CONV_XS2_U64;

    const int b = blockIdx.y;
    const int c0 = blockIdx.x * 128;
    const int tid = threadIdx.x;

    {
        const float* xsrc = x + (size_t)b * 3072;
        #pragma unroll
        for (int i = 0; i < 12; i++) {
            int idx = tid + 256 * i;
            float v = xsrc[idx];
            xs2[idx] = make_float2(v, v);
        }
    }
    for (int idx = tid; idx < CONV_W_U64; idx += 256) {
        int ct = idx & 15;
        int kq = idx >> 4;
        int k = kq >> 2, q = kq & 3;
        int ch = c0 + ct * 8 + 2 * q;
        float a = w[(size_t)ch * 108 + k];
        float bb = w[(size_t)(ch + 1) * 108 + k];
        ws2[idx] = make_float2(a, bb);
    }
    __syncthreads();

    const int ch_tid = tid & 15;
    const int pos_tid = tid >> 4;
    const int ch0 = ch_tid * 8;

    for (int chunk = 0; chunk < 6; chunk++) {
        const int p0 = chunk * 128 + pos_tid * 8;
        int pbase[8];
        #pragma unroll
        for (int pp = 0; pp < 8; pp++) {
            int p = p0 + pp; if (p > 728) p = 728;
            int y = p / 27;
            pbase[pp] = y * 32 + (p - y * 27);
        }
        unsigned long long acc0[8], acc1[8], acc2[8], acc3[8];
        #pragma unroll
        for (int pp = 0; pp < 8; pp++) { acc0[pp] = 0ull; acc1[pp] = 0ull; acc2[pp] = 0ull; acc3[pp] = 0ull; }

        #pragma unroll 1
        for (int c = 0; c < 3; c++) {
            #pragma unroll 1
            for (int i = 0; i < 6; i++) {
                const unsigned long long* xrow = xsu + c * 1024 + i * 32;
                const int kbase = (c * 36 + i * 6) * 4;
                #pragma unroll
                for (int j = 0; j < 6; j++) {
                    const unsigned long long* wk = wsu + (size_t)(kbase + j * 4) * 16 + ch_tid;
                    unsigned long long w0 = wk[0], w1 = wk[16], w2 = wk[32], w3 = wk[48];
                    #pragma unroll
                    for (int pp = 0; pp < 8; pp++) {
                        unsigned long long xx = xrow[pbase[pp] + j];
                        asm("fma.rn.f32x2 %0, %1, %2, %0;" : "+l"(acc0[pp]) : "l"(w0), "l"(xx));
                        asm("fma.rn.f32x2 %0, %1, %2, %0;" : "+l"(acc1[pp]) : "l"(w1), "l"(xx));
                        asm("fma.rn.f32x2 %0, %1, %2, %0;" : "+l"(acc2[pp]) : "l"(w2), "l"(xx));
                        asm("fma.rn.f32x2 %0, %1, %2, %0;" : "+l"(acc3[pp]) : "l"(w3), "l"(xx));
                    }
                }
            }
        }
        #pragma unroll
        for (int pp = 0; pp < 8; pp++) {
            int p = p0 + pp;
            if (p < 729) {
                float* dst = g_conv + ((size_t)(b * NPOS9 + p)) * NC + c0 + ch0;
                float a, bb, cc, dd, e, f, g, h;
                asm("mov.b64 {%0, %1}, %2;" : "=f"(a), "=f"(bb) : "l"(acc0[pp]));
                asm("mov.b64 {%0, %1}, %2;" : "=f"(cc), "=f"(dd) : "l"(acc1[pp]));
                asm("mov.b64 {%0, %1}, %2;" : "=f"(e), "=f"(f) : "l"(acc2[pp]));
                asm("mov.b64 {%0, %1}, %2;" : "=f"(g), "=f"(h) : "l"(acc3[pp]));
                ((float4*)dst)[0] = make_float4(a, bb, cc, dd);
                ((float4*)dst)[1] = make_float4(e, f, g, h);
            }
        }
    }
}

// ---------------------------------------------------------------------------
// select helpers
// ---------------------------------------------------------------------------
__device__ __forceinline__ unsigned f2u(float f) {
    int b = __float_as_int(f);
    return (unsigned)(b ^ ((b >> 31) | 0x80000000));
}
__device__ __forceinline__ float u2f(unsigned u) {
    unsigned b = (u & 0x80000000u) ? (u & 0x7fffffffu) : ~u;
    return __uint_as_float(b);
}
__device__ __forceinline__ int wsum(int v) {
    #pragma unroll
    for (int o = 16; o; o >>= 1) v += __shfl_xor_sync(~0u, v, o);
    return v;
}
__device__ __forceinline__ unsigned wminu(unsigned v) {
    #pragma unroll
    for (int o = 16; o; o >>= 1) v = min(v, (unsigned)__shfl_xor_sync(~0u, v, o));
    return v;
}
__device__ __forceinline__ unsigned wmaxu(unsigned v) {
    #pragma unroll
    for (int o = 16; o; o >>= 1) v = max(v, (unsigned)__shfl_xor_sync(~0u, v, o));
    return v;
}

template<bool MASKED>
__device__ __forceinline__ int hist_sweep(const float4* __restrict__ vsrc,
                                          const float* __restrict__ sbias,
                                          unsigned top1, unsigned top2,
                                          unsigned maskTop, int shift, int lane)
{
    const unsigned bin = lane & 15;
    const unsigned r0 = (bin & 1) ? ~0u : 0u;
    const unsigned r1 = (bin & 2) ? ~0u : 0u;
    const unsigned r2 = (bin & 4) ? ~0u : 0u;
    const unsigned r3 = (bin & 8) ? ~0u : 0u;
    const bool br2 = (lane >= 16);
    int cnt = 0;
    const float4* bs4 = (const float4*)sbias;
    for (int t = 0; t < 16; t++) {
        float4 v4 = __ldg(vsrc + t * 32 + lane);
        float4 b4 = bs4[t * 32 + lane];
        #pragma unroll
        for (int e = 0; e < 4; e++) {
            float v = (&v4.x)[e], bb = (&b4.x)[e];
            unsigned u1 = f2u(bb - v), u2 = f2u(bb + v);
            bool a1 = MASKED ? (((u1 ^ top1) & maskTop) == 0) : true;
            bool a2 = MASKED ? (((u2 ^ top2) & maskTop) == 0) : true;
            unsigned d1 = u1 >> shift, d2 = u2 >> shift;
            unsigned B10 = __ballot_sync(~0u, a1 && (d1 & 1));
            unsigned B11 = __ballot_sync(~0u, a1 && (d1 & 2));
            unsigned B12 = __ballot_sync(~0u, a1 && (d1 & 4));
            unsigned B13 = __ballot_sync(~0u, a1 && (d1 & 8));
            unsigned A1  = MASKED ? __ballot_sync(~0u, a1) : ~0u;
            unsigned B20 = __ballot_sync(~0u, a2 && (d2 & 1));
            unsigned B21 = __ballot_sync(~0u, a2 && (d2 & 2));
            unsigned B22 = __ballot_sync(~0u, a2 && (d2 & 4));
            unsigned B23 = __ballot_sync(~0u, a2 && (d2 & 8));
            unsigned A2  = MASKED ? __ballot_sync(~0u, a2) : ~0u;
            unsigned Bb0 = br2 ? B20 : B10;
            unsigned Bb1 = br2 ? B21 : B11;
            unsigned Bb2 = br2 ? B22 : B12;
            unsigned Bb3 = br2 ? B23 : B13;
            unsigned A   = br2 ? A2  : A1;
            unsigned mm = A & ~((Bb3 ^ r3) | (Bb2 ^ r2) | (Bb1 ^ r1) | (Bb0 ^ r0));
            cnt += __popc(mm);
        }
    }
    return cnt;
}

__device__ __forceinline__ void pick_bins(int cnt, int& rank1, int& rank2,
                                          unsigned& dig1, unsigned& dig2,
                                          int& m1, int& m2, int lane)
{
    int incl = cnt;
    #pragma unroll
    for (int o = 1; o < 16; o <<= 1) {
        int n = __shfl_up_sync(~0u, incl, o, 16);
        if ((lane & 15) >= o) incl += n;
    }
    int excl = incl - cnt;
    int rk = (lane < 16) ? rank1 : rank2;
    bool hit = (rk >= excl) && (rk < incl);
    unsigned bal = __ballot_sync(~0u, hit);
    int src1 = __ffs(bal & 0xFFFFu) - 1;
    int src2 = 31 - __clz(bal & 0xFFFF0000u);
    int nr = rk - excl;
    dig1 = (unsigned)(src1 & 15);
    dig2 = (unsigned)(src2 & 15);
    rank1 = __shfl_sync(~0u, nr, src1);
    rank2 = __shfl_sync(~0u, nr, src2);
    m1 = __shfl_sync(~0u, cnt, src1);
    m2 = __shfl_sync(~0u, cnt, src2);
}

__device__ __forceinline__ void compact_sweep(const float4* __restrict__ vsrc,
                                              const float* __restrict__ sbias,
                                              unsigned top1, unsigned top2,
                                              unsigned maskTop,
                                              unsigned* l1, unsigned* l2,
                                              bool en1, bool en2, int lane)
{
    int n1 = 0, n2 = 0;
    const unsigned lt = (1u << lane) - 1u;
    const float4* bs4 = (const float4*)sbias;
    for (int t = 0; t < 16; t++) {
        float4 v4 = __ldg(vsrc + t * 32 + lane);
        float4 b4 = bs4[t * 32 + lane];
        #pragma unroll
        for (int e = 0; e < 4; e++) {
            float v = (&v4.x)[e], bb = (&b4.x)[e];
            unsigned u1 = f2u(bb - v), u2 = f2u(bb + v);
            bool k1 = en1 && (((u1 ^ top1) & maskTop) == 0);
            bool k2 = en2 && (((u2 ^ top2) & maskTop) == 0);
            unsigned bal1 = __ballot_sync(~0u, k1);
            if (k1) l1[n1 + __popc(bal1 & lt)] = u1;
            n1 += __popc(bal1);
            unsigned bal2 = __ballot_sync(~0u, k2);
            if (k2) l2[n2 + __popc(bal2 & lt)] = u2;
            n2 += __popc(bal2);
        }
    }
}

__device__ __forceinline__ unsigned list_pass(unsigned* L, int& m, int& rank,
                                              int shift, int lane)
{
    const unsigned bin = lane & 15;
    const unsigned r0 = (bin & 1) ? ~0u : 0u;
    const unsigned r1 = (bin & 2) ? ~0u : 0u;
    const unsigned r2 = (bin & 4) ? ~0u : 0u;
    const unsigned r3 = (bin & 8) ? ~0u : 0u;
    const unsigned lt = (1u << lane) - 1u;
    int iters = (m + 31) >> 5;
    int cnt = 0;
    for (int i = 0; i < iters; i++) {
        int idx = i * 32 + lane;
        bool act = idx < m;
        unsigned u = act ? L[idx] : 0u;
        unsigned d = u >> shift;
        unsigned B0 = __ballot_sync(~0u, act && (d & 1));
        unsigned B1 = __ballot_sync(~0u, act && (d & 2));
        unsigned B2 = __ballot_sync(~0u, act && (d & 4));
        unsigned B3 = __ballot_sync(~0u, act && (d & 8));
        unsigned A  = __ballot_sync(~0u, act);
        unsigned mm = A & ~((B3 ^ r3) | (B2 ^ r2) | (B1 ^ r1) | (B0 ^ r0));
        cnt += __popc(mm);
    }
    int incl = cnt;
    #pragma unroll
    for (int o = 1; o < 16; o <<= 1) {
        int n = __shfl_up_sync(~0u, incl, o, 16);
        if ((lane & 15) >= o) incl += n;
    }
    int excl = incl - cnt;
    bool hit = (lane < 16) && (rank >= excl) && (rank < incl);
    unsigned bal = __ballot_sync(~0u, hit);
    int src = __ffs(bal) - 1;
    unsigned dig = (unsigned)src;
    int nr = rank - excl;
    rank = __shfl_sync(~0u, nr, src);
    int w = 0;
    for (int i = 0; i < iters; i++) {
        int idx = i * 32 + lane;
        bool act = idx < m;
        unsigned u = act ? L[idx] : 0u;
        bool keep = act && (((u >> shift) & 15u) == dig);
        unsigned kb = __ballot_sync(~0u, keep);
        if (keep) L[w + __popc(kb & lt)] = u;
        w += __popc(kb);
    }
    m = w;
    return dig;
}

__device__ __forceinline__ unsigned final32(const unsigned* L, int m, int rank, int lane)
{
    unsigned myv = (lane < m) ? L[lane] : 0xFFFFFFFFu;
    int c = 0;
    #pragma unroll
    for (int j = 0; j < 32; j++) {
        unsigned o = __shfl_sync(~0u, myv, j);
        c += (o < myv) || (o == myv && j < lane);
    }
    bool hit = (c == rank) && (lane < m);
    unsigned bal = __ballot_sync(~0u, hit);
    int src = __ffs(bal) - 1;
    return __shfl_sync(~0u, myv, src);
}

__device__ __forceinline__ unsigned solve_list(unsigned* L, int m, int rank,
                                               unsigned tp, int sh0, int lane)
{
    int sh = sh0, m_ = m, r = rank; unsigned tp_ = tp;
    while (m_ > 32 && sh >= 0) {
        unsigned d = list_pass(L, m_, r, sh, lane);
        tp_ |= d << sh; sh -= 4;
    }
    return (m_ > 32) ? tp_ : final32(L, m_, r, lane);
}

__device__ __forceinline__ unsigned solve_list_smart(unsigned* L, int m, int rank,
                                                     unsigned umin, unsigned umax, int lane)
{
    if (umin == umax) return umin;
    int bit = 31 - __clz(umin ^ umax);
    int sh0 = (bit >> 2) << 2;
    unsigned pref = (sh0 >= 28) ? 0u : (umin & (~0u << (sh0 + 4)));
    return solve_list(L, m, rank, pref, sh0, lane);
}

// exact general radix path for one position (rare fallback)
__device__ __noinline__ void general_select(const float4* vsrc, const float* sbias,
                                            unsigned* l1, unsigned* l2, int lane,
                                            unsigned& ans1, unsigned& ans2)
{
    int rank1 = KSEL, rank2 = KSEL;
    unsigned top1 = 0, top2 = 0, maskTop = 0;
    int m1 = NC, m2 = NC;
    int shift = 28;
    unsigned dig1, dig2;
    {
        int cnt = hist_sweep<false>(vsrc, sbias, 0, 0, 0, shift, lane);
        pick_bins(cnt, rank1, rank2, dig1, dig2, m1, m2, lane);
        top1 |= dig1 << shift; top2 |= dig2 << shift;
        maskTop |= 0xFu << shift; shift -= 4;
    }
    while ((m1 > SEL_CAP || m2 > SEL_CAP) && shift >= 0) {
        int cnt = hist_sweep<true>(vsrc, sbias, top1, top2, maskTop, shift, lane);
        pick_bins(cnt, rank1, rank2, dig1, dig2, m1, m2, lane);
        top1 |= dig1 << shift; top2 |= dig2 << shift;
        maskTop |= 0xFu << shift; shift -= 4;
    }
    bool en1 = (m1 <= SEL_CAP), en2 = (m2 <= SEL_CAP);
    compact_sweep(vsrc, sbias, top1, top2, maskTop, l1, l2, en1, en2, lane);
    ans1 = en1 ? solve_list(l1, m1, rank1, top1, shift, lane) : top1;
    ans2 = en2 ? solve_list(l2, m2, rank2, top2, shift, lane) : top2;
}

// ---------------------------------------------------------------------------
// Kernel 1b: exact 819th-smallest of bias (one warp) -> g_t0 window center
// ---------------------------------------------------------------------------
__global__ void t0_kernel(const float* __restrict__ bias)
{
    __shared__ unsigned sk[NC];
    const int lane = threadIdx.x & 31;
    for (int i = lane; i < NC; i += 32) sk[i] = f2u(bias[i]);
    __syncwarp();
    unsigned ans;
    {
        int m = NC, r = KSEL, sh = 28; unsigned tp = 0;
        while (m > 32 && sh >= 0) {
            unsigned d = list_pass(sk, m, r, sh, lane);
            tp |= d << sh; sh -= 4;
        }
        ans = (m > 32) ? tp : final32(sk, m, r, lane);
    }
    if (lane == 0) g_t0 = u2f(ans);
}

// ---------------------------------------------------------------------------
// Kernel 2: windowed select, 2 positions per warp (4 independent chains).
// ---------------------------------------------------------------------------
#define SEL_SMEM (2048 * 4 + 4 * 4 * SEL_CAP * 4)

__global__ void __launch_bounds__(128) select_kernel(const float* __restrict__ bias)
{
    extern __shared__ float smem[];
    float* sbias = smem;                          // 2048 floats
    unsigned* slist = (unsigned*)(smem + 2048);   // 4 warps * 4 * SEL_CAP

    const int tid = threadIdx.x;
    const int wid = tid >> 5, lane = tid & 31;

    {
        const float4* bsrc = (const float4*)bias;
        float4* bdst = (float4*)sbias;
        #pragma unroll
        for (int i = 0; i < 4; i++) bdst[tid + 128 * i] = bsrc[tid + 128 * i];
    }
    __syncthreads();

    const int posA = (blockIdx.x * 4 + wid) * 2;
    const int posB = posA + 1;
    const float4* vsA = (const float4*)(g_conv + (size_t)posA * NC);
    const float4* vsB = (const float4*)(g_conv + (size_t)posB * NC);
    unsigned* lA1 = slist + wid * 4 * SEL_CAP;
    unsigned* lA2 = lA1 + SEL_CAP;
    unsigned* lB1 = lA2 + SEL_CAP;
    unsigned* lB2 = lB1 + SEL_CAP;

    const float t0 = g_t0;
    const float wlo = t0 - WIN, whi = t0 + WIN;
    const unsigned lt = (1u << lane) - 1u;

    int cbA1 = 0, cbA2 = 0, cbB1 = 0, cbB2 = 0;
    int nA1 = 0, nA2 = 0, nB1 = 0, nB2 = 0;
    unsigned mnA1 = ~0u, mxA1 = 0u, mnA2 = ~0u, mxA2 = 0u;
    unsigned mnB1 = ~0u, mxB1 = 0u, mnB2 = ~0u, mxB2 = 0u;

    {
        const float4* bs4 = (const float4*)sbias;
        #pragma unroll 1
        for (int q = 0; q < 4; q++) {
            float4 vA[4], vB[4], bv[4];
            #pragma unroll
            for (int t = 0; t < 4; t++) {
                vA[t] = __ldg(vsA + (q * 4 + t) * 32 + lane);
                vB[t] = __ldg(vsB + (q * 4 + t) * 32 + lane);
                bv[t] = bs4[(q * 4 + t) * 32 + lane];
            }
            #pragma unroll
            for (int t = 0; t < 4; t++) {
                #pragma unroll
                for (int e = 0; e < 4; e++) {
                    float bb = (&bv[t].x)[e];
                    float va = (&vA[t].x)[e], vb = (&vB[t].x)[e];
                    float a1 = bb - va, a2 = bb + va;
                    float b1 = bb - vb, b2 = bb + vb;
                    bool blA1 = a1 < wlo, inA1 = !blA1 && (a1 < whi);
                    bool blA2 = a2 < wlo, inA2 = !blA2 && (a2 < whi);
                    bool blB1 = b1 < wlo, inB1 = !blB1 && (b1 < whi);
                    bool blB2 = b2 < wlo, inB2 = !blB2 && (b2 < whi);
                    cbA1 += blA1; cbA2 += blA2; cbB1 += blB1; cbB2 += blB2;
                    unsigned biA1 = __ballot_sync(~0u, inA1);
                    unsigned biA2 = __ballot_sync(~0u, inA2);
                    unsigned biB1 = __ballot_sync(~0u, inB1);
                    unsigned biB2 = __ballot_sync(~0u, inB2);
                    if (inA1) {
                        unsigned u = f2u(a1);
                        mnA1 = min(mnA1, u); mxA1 = max(mxA1, u);
                        int ix = nA1 + __popc(biA1 & lt); if (ix < SEL_CAP) lA1[ix] = u;
                    }
                    nA1 += __popc(biA1);
                    if (inA2) {
                        unsigned u = f2u(a2);
                        mnA2 = min(mnA2, u); mxA2 = max(mxA2, u);
                        int ix = nA2 + __popc(biA2 & lt); if (ix < SEL_CAP) lA2[ix] = u;
                    }
                    nA2 += __popc(biA2);
                    if (inB1) {
                        unsigned u = f2u(b1);
                        mnB1 = min(mnB1, u); mxB1 = max(mxB1, u);
                        int ix = nB1 + __popc(biB1 & lt); if (ix < SEL_CAP) lB1[ix] = u;
                    }
                    nB1 += __popc(biB1);
                    if (inB2) {
                        unsigned u = f2u(b2);
                        mnB2 = min(mnB2, u); mxB2 = max(mxB2, u);
                        int ix = nB2 + __popc(biB2 & lt); if (ix < SEL_CAP) lB2[ix] = u;
                    }
                    nB2 += __popc(biB2);
                }
            }
        }
    }
    int rA1 = KSEL - wsum(cbA1), rA2 = KSEL - wsum(cbA2);
    int rB1 = KSEL - wsum(cbB1), rB2 = KSEL - wsum(cbB2);
    bool okA = (rA1 >= 0) && (rA1 < nA1) && (nA1 <= SEL_CAP) &&
               (rA2 >= 0) && (rA2 < nA2) && (nA2 <= SEL_CAP);
    bool okB = (rB1 >= 0) && (rB1 < nB1) && (nB1 <= SEL_CAP) &&
               (rB2 >= 0) && (rB2 < nB2) && (nB2 <= SEL_CAP);

    unsigned ansA1, ansA2, ansB1, ansB2;
    if (okA) {
        ansA1 = solve_list_smart(lA1, nA1, rA1, wminu(mnA1), wmaxu(mxA1), lane);
        ansA2 = solve_list_smart(lA2, nA2, rA2, wminu(mnA2), wmaxu(mxA2), lane);
    } else {
        general_select(vsA, sbias, lA1, lA2, lane, ansA1, ansA2);
    }
    if (okB) {
        ansB1 = solve_list_smart(lB1, nB1, rB1, wminu(mnB1), wmaxu(mxB1), lane);
        ansB2 = solve_list_smart(lB2, nB2, rB2, wminu(mnB2), wmaxu(mxB2), lane);
    } else {
        general_select(vsB, sbias, lB1, lB2, lane, ansB1, ansB2);
    }

    if (lane == 0) {
        g_t1[posA] = u2f(ansA1);
        g_t2[posA] = u2f(ansA2);
        g_t1[posB] = u2f(ansB1);
        g_t2[posB] = u2f(ansB2);
    }
}

// ---------------------------------------------------------------------------
// Kernel 3: masks + pooling. Sparse 6x27 map: each wcol/h hits <=2 rows.
// ---------------------------------------------------------------------------
__global__ void __launch_bounds__(128) pool_kernel(const float* __restrict__ bias,
                                                   float* __restrict__ out)
{
    __shared__ float st1[NPOS9], st2[NPOS9];
    __shared__ float sA[6][28];
    __shared__ float4 s4[27 * 32];
    float* srow = (float*)s4;

    const int b = blockIdx.y;
    const int c0 = blockIdx.x * 128;
    const int tid = threadIdx.x;
    const int c = c0 + tid;

    for (int i = tid; i < NPOS9; i += 128) {
        st1[i] = g_t1[b * NPOS9 + i];
        st2[i] = g_t2[b * NPOS9 + i];
    }
    if (tid < 27) {
        int wcol = tid;
        const int sidx[6] = {0, 1, 3, 4, 6, 7};
        #pragma unroll
        for (int i = 0; i < 6; i++) {
            float a = 0.0f;
            #pragma unroll
            for (int q = 0; q < 2; q++) {
                int p = sidx[i] + q;
                int st = 3 * p, en = (st + 5 < 27) ? st + 5 : 27;
                if (wcol >= st && wcol < en) a += 0.5f / (float)(en - st);
            }
            sA[i][wcol] = a;
        }
    }
    __syncthreads();

    const float bc = bias[c];

    float acc1[36], acc2[36];
    #pragma unroll
    for (int k = 0; k < 36; k++) { acc1[k] = 0.0f; acc2[k] = 0.0f; }

    // structural sparsity: nonzero rows of A per column (<=2)
    constexpr int PJ0[27] = {0,0,0,0,0,0,0,0,1,1,1,2,2,2,2,2,2,3,3,3,4,4,4,4,4,4,5};
    constexpr int PJ1[27] = {-1,-1,-1,1,1,1,1,1,-1,2,2,-1,3,3,3,3,3,-1,4,4,-1,5,5,5,5,5,-1};

    #pragma unroll 1
    for (int h = 0; h < 27; h++) {
        const float* rowbase = g_conv + ((size_t)(b * NPOS9 + h * 27)) * NC + c0;
        #pragma unroll
        for (int k = 0; k < 7; k++) {
            int j = tid + 128 * k;
            if (j < 864) {
                int p = j >> 5, cq = j & 31;
                s4[j] = __ldg((const float4*)(rowbase + (size_t)p * NC) + cq);
            }
        }
        __syncthreads();

        float r1[6], r2[6];
        #pragma unroll
        for (int j = 0; j < 6; j++) { r1[j] = 0.0f; r2[j] = 0.0f; }
        const int hbase = h * 27;
        #pragma unroll
        for (int w = 0; w < 27; w++) {
            float v = srow[w * 128 + tid];
            float m1 = (bc - v < st1[hbase + w]) ? 1.0f : 0.0f;
            float m2 = (bc + v < st2[hbase + w]) ? 1.0f : 0.0f;
            {
                const int j = PJ0[w];
                float a = sA[j][w];
                r1[j] += a * m1;
                r2[j] += a * m2;
            }
            if (PJ1[w] >= 0) {
                const int j = PJ1[w];
                float a = sA[j][w];
                r1[j] += a * m1;
                r2[j] += a * m2;
            }
        }
        #pragma unroll
        for (int i = 0; i < 6; i++) {
            float ah = sA[i][h];
            if (ah != 0.0f) {
                #pragma unroll
                for (int j = 0; j < 6; j++) {
                    acc1[i * 6 + j] += ah * r1[j];
                    acc2[i * 6 + j] += ah * r2[j];
                }
            }
        }
        __syncthreads();
    }

    float* o1 = out + ((size_t)(b * NC + c)) * 36;
    float* o2 = o1 + (size_t)NB * NC * 36;
    #pragma unroll
    for (int k = 0; k < 36; k++) { o1[k] = acc1[k]; o2[k] = acc2[k]; }
}

// ---------------------------------------------------------------------------
extern "C" void kernel_launch(void* const* d_in, const int* in_sizes, int n_in,
                              void* d_out, int out_size)
{
    const float* x    = (const float*)d_in[0]; // [64,3,32,32]
    const float* w    = (const float*)d_in[1]; // [2048,3,6,6]
    const float* bias = (const float*)d_in[2]; // [2048]
    float* out = (float*)d_out;                // [2][64,2048,6,6]

    cudaFuncSetAttribute(conv_kernel, cudaFuncAttributeMaxDynamicSharedMemorySize, CONV_SMEM);
    cudaFuncSetAttribute(select_kernel, cudaFuncAttributeMaxDynamicSharedMemorySize, SEL_SMEM);

    conv_kernel<<<dim3(16, 64), 256, CONV_SMEM>>>(x, w);
    t0_kernel<<<1, 32>>>(bias);
    select_kernel<<<TOTPOS / 8, 128, SEL_SMEM>>>(bias);
    pool_kernel<<<dim3(16, 64), 128>>>(bias, out);
}

// round 13
// speedup vs baseline: 1.0801x; 1.0801x over previous
#include <cuda_runtime.h>
#include <cstdint>

#define NB 64
#define NC 2048
#define NPOS9 729          // 27*27
#define TOTPOS (NB*NPOS9)  // 46656
#define KSEL 819
#define SEL_CAP 512
#define WIN 0.28f

__device__ float g_conv[(size_t)NB * NPOS9 * NC];  // NHWC: [b][p][c]
__device__ float g_t1[TOTPOS];
__device__ float g_t2[TOTPOS];
__device__ float g_t0;

// ---------------------------------------------------------------------------
// Kernel 1: conv (VALID, stride 1) -> NHWC scratch.  fp32 via fma.rn.f32x2.
// ---------------------------------------------------------------------------
#define CONV_XS2_U64 3072
#define CONV_W_U64  (108 * 4 * 16)
#define CONV_SMEM ((CONV_XS2_U64 + CONV_W_U64) * 8)

__global__ void __launch_bounds__(256) conv_kernel(const float* __restrict__ x,
                                                   const float* __restrict__ w)
{
    extern __shared__ unsigned long long smem64[];
    float2* xs2 = (float2*)smem64;
    float2* ws2 = (float2*)(smem64 + CONV_XS2_U64);
    const unsigned long long* xsu = smem64;
    const unsigned long long* wsu = smem64 + CONV_XS2_U64;

    const int b = blockIdx.y;
    const int c0 = blockIdx.x * 128;
    const int tid = threadIdx.x;

    {
        const float* xsrc = x + (size_t)b * 3072;
        #pragma unroll
        for (int i = 0; i < 12; i++) {
            int idx = tid + 256 * i;
            float v = xsrc[idx];
            xs2[idx] = make_float2(v, v);
        }
    }
    for (int idx = tid; idx < CONV_W_U64; idx += 256) {
        int ct = idx & 15;
        int kq = idx >> 4;
        int k = kq >> 2, q = kq & 3;
        int ch = c0 + ct * 8 + 2 * q;
        float a = w[(size_t)ch * 108 + k];
        float bb = w[(size_t)(ch + 1) * 108 + k];
        ws2[idx] = make_float2(a, bb);
    }
    __syncthreads();

    const int ch_tid = tid & 15;
    const int pos_tid = tid >> 4;
    const int ch0 = ch_tid * 8;

    for (int chunk = 0; chunk < 6; chunk++) {
        const int p0 = chunk * 128 + pos_tid * 8;
        int pbase[8];
        #pragma unroll
        for (int pp = 0; pp < 8; pp++) {
            int p = p0 + pp; if (p > 728) p = 728;
            int y = p / 27;
            pbase[pp] = y * 32 + (p - y * 27);
        }
        unsigned long long acc0[8], acc1[8], acc2[8], acc3[8];
        #pragma unroll
        for (int pp = 0; pp < 8; pp++) { acc0[pp] = 0ull; acc1[pp] = 0ull; acc2[pp] = 0ull; acc3[pp] = 0ull; }

        #pragma unroll 1
        for (int c = 0; c < 3; c++) {
            #pragma unroll 1
            for (int i = 0; i < 6; i++) {
                const unsigned long long* xrow = xsu + c * 1024 + i * 32;
                const int kbase = (c * 36 + i * 6) * 4;
                #pragma unroll
                for (int j = 0; j < 6; j++) {
                    const unsigned long long* wk = wsu + (size_t)(kbase + j * 4) * 16 + ch_tid;
                    unsigned long long w0 = wk[0], w1 = wk[16], w2 = wk[32], w3 = wk[48];
                    #pragma unroll
                    for (int pp = 0; pp < 8; pp++) {
                        unsigned long long xx = xrow[pbase[pp] + j];
                        asm("fma.rn.f32x2 %0, %1, %2, %0;" : "+l"(acc0[pp]) : "l"(w0), "l"(xx));
                        asm("fma.rn.f32x2 %0, %1, %2, %0;" : "+l"(acc1[pp]) : "l"(w1), "l"(xx));
                        asm("fma.rn.f32x2 %0, %1, %2, %0;" : "+l"(acc2[pp]) : "l"(w2), "l"(xx));
                        asm("fma.rn.f32x2 %0, %1, %2, %0;" : "+l"(acc3[pp]) : "l"(w3), "l"(xx));
                    }
                }
            }
        }
        #pragma unroll
        for (int pp = 0; pp < 8; pp++) {
            int p = p0 + pp;
            if (p < 729) {
                float* dst = g_conv + ((size_t)(b * NPOS9 + p)) * NC + c0 + ch0;
                float a, bb, cc, dd, e, f, g, h;
                asm("mov.b64 {%0, %1}, %2;" : "=f"(a), "=f"(bb) : "l"(acc0[pp]));
                asm("mov.b64 {%0, %1}, %2;" : "=f"(cc), "=f"(dd) : "l"(acc1[pp]));
                asm("mov.b64 {%0, %1}, %2;" : "=f"(e), "=f"(f) : "l"(acc2[pp]));
                asm("mov.b64 {%0, %1}, %2;" : "=f"(g), "=f"(h) : "l"(acc3[pp]));
                ((float4*)dst)[0] = make_float4(a, bb, cc, dd);
                ((float4*)dst)[1] = make_float4(e, f, g, h);
            }
        }
    }
}

// ---------------------------------------------------------------------------
// select helpers
// ---------------------------------------------------------------------------
__device__ __forceinline__ unsigned f2u(float f) {
    int b = __float_as_int(f);
    return (unsigned)(b ^ ((b >> 31) | 0x80000000));
}
__device__ __forceinline__ float u2f(unsigned u) {
    unsigned b = (u & 0x80000000u) ? (u & 0x7fffffffu) : ~u;
    return __uint_as_float(b);
}
__device__ __forceinline__ int wsum(int v) {
    #pragma unroll
    for (int o = 16; o; o >>= 1) v += __shfl_xor_sync(~0u, v, o);
    return v;
}
__device__ __forceinline__ unsigned wminu(unsigned v) {
    #pragma unroll
    for (int o = 16; o; o >>= 1) v = min(v, (unsigned)__shfl_xor_sync(~0u, v, o));
    return v;
}
__device__ __forceinline__ unsigned wmaxu(unsigned v) {
    #pragma unroll
    for (int o = 16; o; o >>= 1) v = max(v, (unsigned)__shfl_xor_sync(~0u, v, o));
    return v;
}

template<bool MASKED>
__device__ __forceinline__ int hist_sweep(const float4* __restrict__ vsrc,
                                          const float* __restrict__ sbias,
                                          unsigned top1, unsigned top2,
                                          unsigned maskTop, int shift, int lane)
{
    const unsigned bin = lane & 15;
    const unsigned r0 = (bin & 1) ? ~0u : 0u;
    const unsigned r1 = (bin & 2) ? ~0u : 0u;
    const unsigned r2 = (bin & 4) ? ~0u : 0u;
    const unsigned r3 = (bin & 8) ? ~0u : 0u;
    const bool br2 = (lane >= 16);
    int cnt = 0;
    const float4* bs4 = (const float4*)sbias;
    for (int t = 0; t < 16; t++) {
        float4 v4 = __ldg(vsrc + t * 32 + lane);
        float4 b4 = bs4[t * 32 + lane];
        #pragma unroll
        for (int e = 0; e < 4; e++) {
            float v = (&v4.x)[e], bb = (&b4.x)[e];
            unsigned u1 = f2u(bb - v), u2 = f2u(bb + v);
            bool a1 = MASKED ? (((u1 ^ top1) & maskTop) == 0) : true;
            bool a2 = MASKED ? (((u2 ^ top2) & maskTop) == 0) : true;
            unsigned d1 = u1 >> shift, d2 = u2 >> shift;
            unsigned B10 = __ballot_sync(~0u, a1 && (d1 & 1));
            unsigned B11 = __ballot_sync(~0u, a1 && (d1 & 2));
            unsigned B12 = __ballot_sync(~0u, a1 && (d1 & 4));
            unsigned B13 = __ballot_sync(~0u, a1 && (d1 & 8));
            unsigned A1  = MASKED ? __ballot_sync(~0u, a1) : ~0u;
            unsigned B20 = __ballot_sync(~0u, a2 && (d2 & 1));
            unsigned B21 = __ballot_sync(~0u, a2 && (d2 & 2));
            unsigned B22 = __ballot_sync(~0u, a2 && (d2 & 4));
            unsigned B23 = __ballot_sync(~0u, a2 && (d2 & 8));
            unsigned A2  = MASKED ? __ballot_sync(~0u, a2) : ~0u;
            unsigned Bb0 = br2 ? B20 : B10;
            unsigned Bb1 = br2 ? B21 : B11;
            unsigned Bb2 = br2 ? B22 : B12;
            unsigned Bb3 = br2 ? B23 : B13;
            unsigned A   = br2 ? A2  : A1;
            unsigned mm = A & ~((Bb3 ^ r3) | (Bb2 ^ r2) | (Bb1 ^ r1) | (Bb0 ^ r0));
            cnt += __popc(mm);
        }
    }
    return cnt;
}

__device__ __forceinline__ void pick_bins(int cnt, int& rank1, int& rank2,
                                          unsigned& dig1, unsigned& dig2,
                                          int& m1, int& m2, int lane)
{
    int incl = cnt;
    #pragma unroll
    for (int o = 1; o < 16; o <<= 1) {
        int n = __shfl_up_sync(~0u, incl, o, 16);
        if ((lane & 15) >= o) incl += n;
    }
    int excl = incl - cnt;
    int rk = (lane < 16) ? rank1 : rank2;
    bool hit = (rk >= excl) && (rk < incl);
    unsigned bal = __ballot_sync(~0u, hit);
    int src1 = __ffs(bal & 0xFFFFu) - 1;
    int src2 = 31 - __clz(bal & 0xFFFF0000u);
    int nr = rk - excl;
    dig1 = (unsigned)(src1 & 15);
    dig2 = (unsigned)(src2 & 15);
    rank1 = __shfl_sync(~0u, nr, src1);
    rank2 = __shfl_sync(~0u, nr, src2);
    m1 = __shfl_sync(~0u, cnt, src1);
    m2 = __shfl_sync(~0u, cnt, src2);
}

__device__ __forceinline__ void compact_sweep(const float4* __restrict__ vsrc,
                                              const float* __restrict__ sbias,
                                              unsigned top1, unsigned top2,
                                              unsigned maskTop,
                                              unsigned* l1, unsigned* l2,
                                              bool en1, bool en2, int lane)
{
    int n1 = 0, n2 = 0;
    const unsigned lt = (1u << lane) - 1u;
    const float4* bs4 = (const float4*)sbias;
    for (int t = 0; t < 16; t++) {
        float4 v4 = __ldg(vsrc + t * 32 + lane);
        float4 b4 = bs4[t * 32 + lane];
        #pragma unroll
        for (int e = 0; e < 4; e++) {
            float v = (&v4.x)[e], bb = (&b4.x)[e];
            unsigned u1 = f2u(bb - v), u2 = f2u(bb + v);
            bool k1 = en1 && (((u1 ^ top1) & maskTop) == 0);
            bool k2 = en2 && (((u2 ^ top2) & maskTop) == 0);
            unsigned bal1 = __ballot_sync(~0u, k1);
            if (k1) l1[n1 + __popc(bal1 & lt)] = u1;
            n1 += __popc(bal1);
            unsigned bal2 = __ballot_sync(~0u, k2);
            if (k2) l2[n2 + __popc(bal2 & lt)] = u2;
            n2 += __popc(bal2);
        }
    }
}

__device__ __forceinline__ unsigned list_pass(unsigned* L, int& m, int& rank,
                                              int shift, int lane)
{
    const unsigned bin = lane & 15;
    const unsigned r0 = (bin & 1) ? ~0u : 0u;
    const unsigned r1 = (bin & 2) ? ~0u : 0u;
    const unsigned r2 = (bin & 4) ? ~0u : 0u;
    const unsigned r3 = (bin & 8) ? ~0u : 0u;
    const unsigned lt = (1u << lane) - 1u;
    int iters = (m + 31) >> 5;
    int cnt = 0;
    for (int i = 0; i < iters; i++) {
        int idx = i * 32 + lane;
        bool act = idx < m;
        unsigned u = act ? L[idx] : 0u;
        unsigned d = u >> shift;
        unsigned B0 = __ballot_sync(~0u, act && (d & 1));
        unsigned B1 = __ballot_sync(~0u, act && (d & 2));
        unsigned B2 = __ballot_sync(~0u, act && (d & 4));
        unsigned B3 = __ballot_sync(~0u, act && (d & 8));
        unsigned A  = __ballot_sync(~0u, act);
        unsigned mm = A & ~((B3 ^ r3) | (B2 ^ r2) | (B1 ^ r1) | (B0 ^ r0));
        cnt += __popc(mm);
    }
    int incl = cnt;
    #pragma unroll
    for (int o = 1; o < 16; o <<= 1) {
        int n = __shfl_up_sync(~0u, incl, o, 16);
        if ((lane & 15) >= o) incl += n;
    }
    int excl = incl - cnt;
    bool hit = (lane < 16) && (rank >= excl) && (rank < incl);
    unsigned bal = __ballot_sync(~0u, hit);
    int src = __ffs(bal) - 1;
    unsigned dig = (unsigned)src;
    int nr = rank - excl;
    rank = __shfl_sync(~0u, nr, src);
    int w = 0;
    for (int i = 0; i < iters; i++) {
        int idx = i * 32 + lane;
        bool act = idx < m;
        unsigned u = act ? L[idx] : 0u;
        bool keep = act && (((u >> shift) & 15u) == dig);
        unsigned kb = __ballot_sync(~0u, keep);
        if (keep) L[w + __popc(kb & lt)] = u;
        w += __popc(kb);
    }
    m = w;
    return dig;
}

__device__ __forceinline__ unsigned final32(const unsigned* L, int m, int rank, int lane)
{
    unsigned myv = (lane < m) ? L[lane] : 0xFFFFFFFFu;
    int c = 0;
    #pragma unroll
    for (int j = 0; j < 32; j++) {
        unsigned o = __shfl_sync(~0u, myv, j);
        c += (o < myv) || (o == myv && j < lane);
    }
    bool hit = (c == rank) && (lane < m);
    unsigned bal = __ballot_sync(~0u, hit);
    int src = __ffs(bal) - 1;
    return __shfl_sync(~0u, myv, src);
}

__device__ __forceinline__ unsigned solve_list(unsigned* L, int m, int rank,
                                               unsigned tp, int sh0, int lane)
{
    int sh = sh0, m_ = m, r = rank; unsigned tp_ = tp;
    while (m_ > 32 && sh >= 0) {
        unsigned d = list_pass(L, m_, r, sh, lane);
        tp_ |= d << sh; sh -= 4;
    }
    return (m_ > 32) ? tp_ : final32(L, m_, r, lane);
}

__device__ __forceinline__ unsigned solve_list_smart(unsigned* L, int m, int rank,
                                                     unsigned umin, unsigned umax, int lane)
{
    if (umin == umax) return umin;
    int bit = 31 - __clz(umin ^ umax);
    int sh0 = (bit >> 2) << 2;
    unsigned pref = (sh0 >= 28) ? 0u : (umin & (~0u << (sh0 + 4)));
    return solve_list(L, m, rank, pref, sh0, lane);
}

// ---------------------------------------------------------------------------
// Kernel 1b: exact 819th-smallest of bias (one warp) -> g_t0 window center
// ---------------------------------------------------------------------------
__global__ void t0_kernel(const float* __restrict__ bias)
{
    __shared__ unsigned sk[NC];
    const int lane = threadIdx.x & 31;
    for (int i = lane; i < NC; i += 32) sk[i] = f2u(bias[i]);
    __syncwarp();
    unsigned ans;
    {
        int m = NC, r = KSEL, sh = 28; unsigned tp = 0;
        while (m > 32 && sh >= 0) {
            unsigned d = list_pass(sk, m, r, sh, lane);
            tp |= d << sh; sh -= 4;
        }
        ans = (m > 32) ? tp : final32(sk, m, r, lane);
    }
    if (lane == 0) g_t0 = u2f(ans);
}

// ---------------------------------------------------------------------------
// Kernel 2: windowed select around g_t0 (R11 version, 1 position/warp).
// ---------------------------------------------------------------------------
#define SEL_SMEM (2048 * 4 + 4 * 2 * SEL_CAP * 4)

__global__ void __launch_bounds__(128) select_kernel(const float* __restrict__ bias)
{
    extern __shared__ float smem[];
    float* sbias = smem;                          // 2048 floats
    unsigned* slist = (unsigned*)(smem + 2048);   // 4 warps * 2 * SEL_CAP

    const int tid = threadIdx.x;
    const int wid = tid >> 5, lane = tid & 31;

    {
        const float4* bsrc = (const float4*)bias;
        float4* bdst = (float4*)sbias;
        #pragma unroll
        for (int i = 0; i < 4; i++) bdst[tid + 128 * i] = bsrc[tid + 128 * i];
    }
    __syncthreads();

    const int pos = blockIdx.x * 4 + wid;
    const float4* vsrc = (const float4*)(g_conv + (size_t)pos * NC);
    unsigned* l1 = slist + wid * 2 * SEL_CAP;
    unsigned* l2 = l1 + SEL_CAP;

    const float t0 = g_t0;
    const float wlo = t0 - WIN, whi = t0 + WIN;
    const unsigned lt = (1u << lane) - 1u;

    int cb1 = 0, cb2 = 0;
    int n1 = 0, n2 = 0;
    unsigned mn1 = 0xFFFFFFFFu, mx1 = 0u, mn2 = 0xFFFFFFFFu, mx2 = 0u;
    {
        const float4* bs4 = (const float4*)sbias;
        #pragma unroll 1
        for (int half = 0; half < 2; half++) {
            float4 vv[8], bv[8];
            #pragma unroll
            for (int t = 0; t < 8; t++) {
                vv[t] = __ldg(vsrc + (half * 8 + t) * 32 + lane);
                bv[t] = bs4[(half * 8 + t) * 32 + lane];
            }
            #pragma unroll
            for (int t = 0; t < 8; t++) {
                #pragma unroll
                for (int e = 0; e < 4; e++) {
                    float v = (&vv[t].x)[e], bb = (&bv[t].x)[e];
                    float k1 = bb - v, k2 = bb + v;
                    bool below1 = k1 < wlo;
                    bool in1 = !below1 && (k1 < whi);
                    bool below2 = k2 < wlo;
                    bool in2 = !below2 && (k2 < whi);
                    cb1 += below1;
                    cb2 += below2;
                    unsigned bi1 = __ballot_sync(~0u, in1);
                    if (in1) {
                        unsigned u1 = f2u(k1);
                        mn1 = min(mn1, u1); mx1 = max(mx1, u1);
                        int ix = n1 + __popc(bi1 & lt); if (ix < SEL_CAP) l1[ix] = u1;
                    }
                    n1 += __popc(bi1);
                    unsigned bi2 = __ballot_sync(~0u, in2);
                    if (in2) {
                        unsigned u2 = f2u(k2);
                        mn2 = min(mn2, u2); mx2 = max(mx2, u2);
                        int ix = n2 + __popc(bi2 & lt); if (ix < SEL_CAP) l2[ix] = u2;
                    }
                    n2 += __popc(bi2);
                }
            }
        }
    }
    int tb1 = wsum(cb1), tb2 = wsum(cb2);
    int r1 = KSEL - tb1, r2 = KSEL - tb2;
    bool ok1 = (r1 >= 0) && (r1 < n1) && (n1 <= SEL_CAP);
    bool ok2 = (r2 >= 0) && (r2 < n2) && (n2 <= SEL_CAP);

    unsigned ansu1, ansu2;
    if (ok1 && ok2) {
        mn1 = wminu(mn1); mx1 = wmaxu(mx1);
        mn2 = wminu(mn2); mx2 = wmaxu(mx2);
        ansu1 = solve_list_smart(l1, n1, r1, mn1, mx1, lane);
        ansu2 = solve_list_smart(l2, n2, r2, mn2, mx2, lane);
    } else {
        int rank1 = KSEL, rank2 = KSEL;
        unsigned top1 = 0, top2 = 0, maskTop = 0;
        int m1 = NC, m2 = NC;
        int shift = 28;
        unsigned dig1, dig2;
        {
            int cnt = hist_sweep<false>(vsrc, sbias, 0, 0, 0, shift, lane);
            pick_bins(cnt, rank1, rank2, dig1, dig2, m1, m2, lane);
            top1 |= dig1 << shift; top2 |= dig2 << shift;
            maskTop |= 0xFu << shift; shift -= 4;
        }
        while ((m1 > SEL_CAP || m2 > SEL_CAP) && shift >= 0) {
            int cnt = hist_sweep<true>(vsrc, sbias, top1, top2, maskTop, shift, lane);
            pick_bins(cnt, rank1, rank2, dig1, dig2, m1, m2, lane);
            top1 |= dig1 << shift; top2 |= dig2 << shift;
            maskTop |= 0xFu << shift; shift -= 4;
        }
        bool en1 = (m1 <= SEL_CAP), en2 = (m2 <= SEL_CAP);
        compact_sweep(vsrc, sbias, top1, top2, maskTop, l1, l2, en1, en2, lane);
        ansu1 = en1 ? solve_list(l1, m1, rank1, top1, shift, lane) : top1;
        ansu2 = en2 ? solve_list(l2, m2, rank2, top2, shift, lane) : top2;
    }

    if (lane == 0) {
        g_t1[pos] = u2f(ansu1);
        g_t2[pos] = u2f(ansu2);
    }
}

// ---------------------------------------------------------------------------
// Kernel 3: masks + pooling. Sparse A + cp.async double-buffered staging.
// ---------------------------------------------------------------------------
__device__ __forceinline__ unsigned smem_u32(const void* p) {
    unsigned a;
    asm("{ .reg .u64 t; cvta.to.shared.u64 t, %1; cvt.u32.u64 %0, t; }" : "=r"(a) : "l"(p));
    return a;
}

__global__ void __launch_bounds__(128) pool_kernel(const float* __restrict__ bias,
                                                   float* __restrict__ out)
{
    __shared__ float st1[NPOS9], st2[NPOS9];
    __shared__ float sA[6][28];
    __shared__ float4 s4[2][27 * 32];   // double-buffered h-row slabs

    const int b = blockIdx.y;
    const int c0 = blockIdx.x * 128;
    const int tid = threadIdx.x;
    const int c = c0 + tid;

    for (int i = tid; i < NPOS9; i += 128) {
        st1[i] = g_t1[b * NPOS9 + i];
        st2[i] = g_t2[b * NPOS9 + i];
    }
    if (tid < 27) {
        int wcol = tid;
        const int sidx[6] = {0, 1, 3, 4, 6, 7};
        #pragma unroll
        for (int i = 0; i < 6; i++) {
            float a = 0.0f;
            #pragma unroll
            for (int q = 0; q < 2; q++) {
                int p = sidx[i] + q;
                int st = 3 * p, en = (st + 5 < 27) ? st + 5 : 27;
                if (wcol >= st && wcol < en) a += 0.5f / (float)(en - st);
            }
            sA[i][wcol] = a;
        }
    }

    const float bc = bias[c];
    const float* base = g_conv + ((size_t)(b * NPOS9)) * NC + c0;

    // async stage of one h-row (27 pos x 128 ch = 864 float4)
    auto stage = [&](int h, int buf) {
        const float* rowbase = base + (size_t)(h * 27) * NC;
        unsigned sdst = smem_u32(&s4[buf][0]);
        #pragma unroll
        for (int k = 0; k < 7; k++) {
            int j = tid + 128 * k;
            if (j < 864) {
                int p = j >> 5, cq = j & 31;
                const float4* gp = (const float4*)(rowbase + (size_t)p * NC) + cq;
                asm volatile("cp.async.cg.shared.global [%0], [%1], 16;"
                             :: "r"(sdst + j * 16), "l"(gp));
            }
        }
        asm volatile("cp.async.commit_group;");
    };

    float acc1[36], acc2[36];
    #pragma unroll
    for (int k = 0; k < 36; k++) { acc1[k] = 0.0f; acc2[k] = 0.0f; }

    constexpr int PJ0[27] = {0,0,0,0,0,0,0,0,1,1,1,2,2,2,2,2,2,3,3,3,4,4,4,4,4,4,5};
    constexpr int PJ1[27] = {-1,-1,-1,1,1,1,1,1,-1,2,2,-1,3,3,3,3,3,-1,4,4,-1,5,5,5,5,5,-1};

    stage(0, 0);
    asm volatile("cp.async.wait_group 0;");
    __syncthreads();

    #pragma unroll 1
    for (int h = 0; h < 27; h++) {
        if (h + 1 < 27) stage(h + 1, (h + 1) & 1);

        const float* srow = (const float*)&s4[h & 1][0];
        float r1[6], r2[6];
        #pragma unroll
        for (int j = 0; j < 6; j++) { r1[j] = 0.0f; r2[j] = 0.0f; }
        const int hbase = h * 27;
        #pragma unroll
        for (int w = 0; w < 27; w++) {
            float v = srow[w * 128 + tid];
            float m1 = (bc - v < st1[hbase + w]) ? 1.0f : 0.0f;
            float m2 = (bc + v < st2[hbase + w]) ? 1.0f : 0.0f;
            {
                const int j = PJ0[w];
                float a = sA[j][w];
                r1[j] += a * m1;
                r2[j] += a * m2;
            }
            if (PJ1[w] >= 0) {
                const int j = PJ1[w];
                float a = sA[j][w];
                r1[j] += a * m1;
                r2[j] += a * m2;
            }
        }
        #pragma unroll
        for (int i = 0; i < 6; i++) {
            float ah = sA[i][h];
            if (ah != 0.0f) {
                #pragma unroll
                for (int j = 0; j < 6; j++) {
                    acc1[i * 6 + j] += ah * r1[j];
                    acc2[i * 6 + j] += ah * r2[j];
                }
            }
        }
        asm volatile("cp.async.wait_group 0;");
        __syncthreads();
    }

    float* o1 = out + ((size_t)(b * NC + c)) * 36;
    float* o2 = o1 + (size_t)NB * NC * 36;
    #pragma unroll
    for (int k = 0; k < 36; k++) { o1[k] = acc1[k]; o2[k] = acc2[k]; }
}

// ---------------------------------------------------------------------------
extern "C" void kernel_launch(void* const* d_in, const int* in_sizes, int n_in,
                              void* d_out, int out_size)
{
    const float* x    = (const float*)d_in[0]; // [64,3,32,32]
    const float* w    = (const float*)d_in[1]; // [2048,3,6,6]
    const float* bias = (const float*)d_in[2]; // [2048]
    float* out = (float*)d_out;                // [2][64,2048,6,6]

    cudaFuncSetAttribute(conv_kernel, cudaFuncAttributeMaxDynamicSharedMemorySize, CONV_SMEM);
    cudaFuncSetAttribute(select_kernel, cudaFuncAttributeMaxDynamicSharedMemorySize, SEL_SMEM);

    conv_kernel<<<dim3(16, 64), 256, CONV_SMEM>>>(x, w);
    t0_kernel<<<1, 32>>>(bias);
    select_kernel<<<TOTPOS / 4, 128, SEL_SMEM>>>(bias);
    pool_kernel<<<dim3(16, 64), 128>>>(bias, out);
}

// round 15
// speedup vs baseline: 1.2573x; 1.1641x over previous
#include <cuda_runtime.h>
#include <cstdint>

#define NB 64
#define NC 2048
#define NPOS9 729          // 27*27
#define TOTPOS (NB*NPOS9)  // 46656
#define KSEL 819
#define SEL_CAP 512
#define WIN 0.16f

__device__ float g_conv[(size_t)NB * NPOS9 * NC];  // NHWC: [b][p][c]
__device__ float g_t1[TOTPOS];
__device__ float g_t2[TOTPOS];
__device__ float g_t0;

// ---------------------------------------------------------------------------
// Kernel 1: conv (VALID, stride 1) -> NHWC scratch.  fp32 via fma.rn.f32x2.
// ---------------------------------------------------------------------------
#define CONV_XS2_U64 3072
#define CONV_W_U64  (108 * 4 * 16)
#define CONV_SMEM ((CONV_XS2_U64 + CONV_W_U64) * 8)

__global__ void __launch_bounds__(256) conv_kernel(const float* __restrict__ x,
                                                   const float* __restrict__ w)
{
    extern __shared__ unsigned long long smem64[];
    float2* xs2 = (float2*)smem64;
    float2* ws2 = (float2*)(smem64 + CONV_XS2_U64);
    const unsigned long long* xsu = smem64;
    const unsigned long long* wsu = smem64 + CONV_XS2_U64;

    const int b = blockIdx.y;
    const int c0 = blockIdx.x * 128;
    const int tid = threadIdx.x;

    {
        const float* xsrc = x + (size_t)b * 3072;
        #pragma unroll
        for (int i = 0; i < 12; i++) {
            int idx = tid + 256 * i;
            float v = xsrc[idx];
            xs2[idx] = make_float2(v, v);
        }
    }
    for (int idx = tid; idx < CONV_W_U64; idx += 256) {
        int ct = idx & 15;
        int kq = idx >> 4;
        int k = kq >> 2, q = kq & 3;
        int ch = c0 + ct * 8 + 2 * q;
        float a = w[(size_t)ch * 108 + k];
        float bb = w[(size_t)(ch + 1) * 108 + k];
        ws2[idx] = make_float2(a, bb);
    }
    __syncthreads();

    const int ch_tid = tid & 15;
    const int pos_tid = tid >> 4;
    const int ch0 = ch_tid * 8;

    for (int chunk = 0; chunk < 6; chunk++) {
        const int p0 = chunk * 128 + pos_tid * 8;
        int pbase[8];
        #pragma unroll
        for (int pp = 0; pp < 8; pp++) {
            int p = p0 + pp; if (p > 728) p = 728;
            int y = p / 27;
            pbase[pp] = y * 32 + (p - y * 27);
        }
        unsigned long long acc0[8], acc1[8], acc2[8], acc3[8];
        #pragma unroll
        for (int pp = 0; pp < 8; pp++) { acc0[pp] = 0ull; acc1[pp] = 0ull; acc2[pp] = 0ull; acc3[pp] = 0ull; }

        #pragma unroll 1
        for (int c = 0; c < 3; c++) {
            #pragma unroll 2
            for (int i = 0; i < 6; i++) {
                const unsigned long long* xrow = xsu + c * 1024 + i * 32;
                const int kbase = (c * 36 + i * 6) * 4;
                #pragma unroll
                for (int j = 0; j < 6; j++) {
                    const unsigned long long* wk = wsu + (size_t)(kbase + j * 4) * 16 + ch_tid;
                    unsigned long long w0 = wk[0], w1 = wk[16], w2 = wk[32], w3 = wk[48];
                    #pragma unroll
                    for (int pp = 0; pp < 8; pp++) {
                        unsigned long long xx = xrow[pbase[pp] + j];
                        asm("fma.rn.f32x2 %0, %1, %2, %0;" : "+l"(acc0[pp]) : "l"(w0), "l"(xx));
                        asm("fma.rn.f32x2 %0, %1, %2, %0;" : "+l"(acc1[pp]) : "l"(w1), "l"(xx));
                        asm("fma.rn.f32x2 %0, %1, %2, %0;" : "+l"(acc2[pp]) : "l"(w2), "l"(xx));
                        asm("fma.rn.f32x2 %0, %1, %2, %0;" : "+l"(acc3[pp]) : "l"(w3), "l"(xx));
                    }
                }
            }
        }
        #pragma unroll
        for (int pp = 0; pp < 8; pp++) {
            int p = p0 + pp;
            if (p < 729) {
                float* dst = g_conv + ((size_t)(b * NPOS9 + p)) * NC + c0 + ch0;
                float a, bb, cc, dd, e, f, g, h;
                asm("mov.b64 {%0, %1}, %2;" : "=f"(a), "=f"(bb) : "l"(acc0[pp]));
                asm("mov.b64 {%0, %1}, %2;" : "=f"(cc), "=f"(dd) : "l"(acc1[pp]));
                asm("mov.b64 {%0, %1}, %2;" : "=f"(e), "=f"(f) : "l"(acc2[pp]));
                asm("mov.b64 {%0, %1}, %2;" : "=f"(g), "=f"(h) : "l"(acc3[pp]));
                ((float4*)dst)[0] = make_float4(a, bb, cc, dd);
                ((float4*)dst)[1] = make_float4(e, f, g, h);
            }
        }
    }
}

// ---------------------------------------------------------------------------
// select helpers
// ---------------------------------------------------------------------------
__device__ __forceinline__ unsigned f2u(float f) {
    int b = __float_as_int(f);
    return (unsigned)(b ^ ((b >> 31) | 0x80000000));
}
__device__ __forceinline__ float u2f(unsigned u) {
    unsigned b = (u & 0x80000000u) ? (u & 0x7fffffffu) : ~u;
    return __uint_as_float(b);
}
__device__ __forceinline__ int wsum(int v) {
    #pragma unroll
    for (int o = 16; o; o >>= 1) v += __shfl_xor_sync(~0u, v, o);
    return v;
}
__device__ __forceinline__ unsigned wminu(unsigned v) {
    #pragma unroll
    for (int o = 16; o; o >>= 1) v = min(v, (unsigned)__shfl_xor_sync(~0u, v, o));
    return v;
}
__device__ __forceinline__ unsigned wmaxu(unsigned v) {
    #pragma unroll
    for (int o = 16; o; o >>= 1) v = max(v, (unsigned)__shfl_xor_sync(~0u, v, o));
    return v;
}

template<bool MASKED>
__device__ __forceinline__ int hist_sweep(const float4* __restrict__ vsrc,
                                          const float* __restrict__ sbias,
                                          unsigned top1, unsigned top2,
                                          unsigned maskTop, int shift, int lane)
{
    const unsigned bin = lane & 15;
    const unsigned r0 = (bin & 1) ? ~0u : 0u;
    const unsigned r1 = (bin & 2) ? ~0u : 0u;
    const unsigned r2 = (bin & 4) ? ~0u : 0u;
    const unsigned r3 = (bin & 8) ? ~0u : 0u;
    const bool br2 = (lane >= 16);
    int cnt = 0;
    const float4* bs4 = (const float4*)sbias;
    for (int t = 0; t < 16; t++) {
        float4 v4 = __ldg(vsrc + t * 32 + lane);
        float4 b4 = bs4[t * 32 + lane];
        #pragma unroll
        for (int e = 0; e < 4; e++) {
            float v = (&v4.x)[e], bb = (&b4.x)[e];
            unsigned u1 = f2u(bb - v), u2 = f2u(bb + v);
            bool a1 = MASKED ? (((u1 ^ top1) & maskTop) == 0) : true;
            bool a2 = MASKED ? (((u2 ^ top2) & maskTop) == 0) : true;
            unsigned d1 = u1 >> shift, d2 = u2 >> shift;
            unsigned B10 = __ballot_sync(~0u, a1 && (d1 & 1));
            unsigned B11 = __ballot_sync(~0u, a1 && (d1 & 2));
            unsigned B12 = __ballot_sync(~0u, a1 && (d1 & 4));
            unsigned B13 = __ballot_sync(~0u, a1 && (d1 & 8));
            unsigned A1  = MASKED ? __ballot_sync(~0u, a1) : ~0u;
            unsigned B20 = __ballot_sync(~0u, a2 && (d2 & 1));
            unsigned B21 = __ballot_sync(~0u, a2 && (d2 & 2));
            unsigned B22 = __ballot_sync(~0u, a2 && (d2 & 4));
            unsigned B23 = __ballot_sync(~0u, a2 && (d2 & 8));
            unsigned A2  = MASKED ? __ballot_sync(~0u, a2) : ~0u;
            unsigned Bb0 = br2 ? B20 : B10;
            unsigned Bb1 = br2 ? B21 : B11;
            unsigned Bb2 = br2 ? B22 : B12;
            unsigned Bb3 = br2 ? B23 : B13;
            unsigned A   = br2 ? A2  : A1;
            unsigned mm = A & ~((Bb3 ^ r3) | (Bb2 ^ r2) | (Bb1 ^ r1) | (Bb0 ^ r0));
            cnt += __popc(mm);
        }
    }
    return cnt;
}

__device__ __forceinline__ void pick_bins(int cnt, int& rank1, int& rank2,
                                          unsigned& dig1, unsigned& dig2,
                                          int& m1, int& m2, int lane)
{
    int incl = cnt;
    #pragma unroll
    for (int o = 1; o < 16; o <<= 1) {
        int n = __shfl_up_sync(~0u, incl, o, 16);
        if ((lane & 15) >= o) incl += n;
    }
    int excl = incl - cnt;
    int rk = (lane < 16) ? rank1 : rank2;
    bool hit = (rk >= excl) && (rk < incl);
    unsigned bal = __ballot_sync(~0u, hit);
    int src1 = __ffs(bal & 0xFFFFu) - 1;
    int src2 = 31 - __clz(bal & 0xFFFF0000u);
    int nr = rk - excl;
    dig1 = (unsigned)(src1 & 15);
    dig2 = (unsigned)(src2 & 15);
    rank1 = __shfl_sync(~0u, nr, src1);
    rank2 = __shfl_sync(~0u, nr, src2);
    m1 = __shfl_sync(~0u, cnt, src1);
    m2 = __shfl_sync(~0u, cnt, src2);
}

__device__ __forceinline__ void compact_sweep(const float4* __restrict__ vsrc,
                                              const float* __restrict__ sbias,
                                              unsigned top1, unsigned top2,
                                              unsigned maskTop,
                                              unsigned* l1, unsigned* l2,
                                              bool en1, bool en2, int lane)
{
    int n1 = 0, n2 = 0;
    const unsigned lt = (1u << lane) - 1u;
    const float4* bs4 = (const float4*)sbias;
    for (int t = 0; t < 16; t++) {
        float4 v4 = __ldg(vsrc + t * 32 + lane);
        float4 b4 = bs4[t * 32 + lane];
        #pragma unroll
        for (int e = 0; e < 4; e++) {
            float v = (&v4.x)[e], bb = (&b4.x)[e];
            unsigned u1 = f2u(bb - v), u2 = f2u(bb + v);
            bool k1 = en1 && (((u1 ^ top1) & maskTop) == 0);
            bool k2 = en2 && (((u2 ^ top2) & maskTop) == 0);
            unsigned bal1 = __ballot_sync(~0u, k1);
            if (k1) l1[n1 + __popc(bal1 & lt)] = u1;
            n1 += __popc(bal1);
            unsigned bal2 = __ballot_sync(~0u, k2);
            if (k2) l2[n2 + __popc(bal2 & lt)] = u2;
            n2 += __popc(bal2);
        }
    }
}

__device__ __forceinline__ unsigned list_pass(unsigned* L, int& m, int& rank,
                                              int shift, int lane)
{
    const unsigned bin = lane & 15;
    const unsigned r0 = (bin & 1) ? ~0u : 0u;
    const unsigned r1 = (bin & 2) ? ~0u : 0u;
    const unsigned r2 = (bin & 4) ? ~0u : 0u;
    const unsigned r3 = (bin & 8) ? ~0u : 0u;
    const unsigned lt = (1u << lane) - 1u;
    int iters = (m + 31) >> 5;
    int cnt = 0;
    for (int i = 0; i < iters; i++) {
        int idx = i * 32 + lane;
        bool act = idx < m;
        unsigned u = act ? L[idx] : 0u;
        unsigned d = u >> shift;
        unsigned B0 = __ballot_sync(~0u, act && (d & 1));
        unsigned B1 = __ballot_sync(~0u, act && (d & 2));
        unsigned B2 = __ballot_sync(~0u, act && (d & 4));
        unsigned B3 = __ballot_sync(~0u, act && (d & 8));
        unsigned A  = __ballot_sync(~0u, act);
        unsigned mm = A & ~((B3 ^ r3) | (B2 ^ r2) | (B1 ^ r1) | (B0 ^ r0));
        cnt += __popc(mm);
    }
    int incl = cnt;
    #pragma unroll
    for (int o = 1; o < 16; o <<= 1) {
        int n = __shfl_up_sync(~0u, incl, o, 16);
        if ((lane & 15) >= o) incl += n;
    }
    int excl = incl - cnt;
    bool hit = (lane < 16) && (rank >= excl) && (rank < incl);
    unsigned bal = __ballot_sync(~0u, hit);
    int src = __ffs(bal) - 1;
    unsigned dig = (unsigned)src;
    int nr = rank - excl;
    rank = __shfl_sync(~0u, nr, src);
    int w = 0;
    for (int i = 0; i < iters; i++) {
        int idx = i * 32 + lane;
        bool act = idx < m;
        unsigned u = act ? L[idx] : 0u;
        bool keep = act && (((u >> shift) & 15u) == dig);
        unsigned kb = __ballot_sync(~0u, keep);
        if (keep) L[w + __popc(kb & lt)] = u;
        w += __popc(kb);
    }
    m = w;
    return dig;
}

__device__ __forceinline__ unsigned final32(const unsigned* L, int m, int rank, int lane)
{
    unsigned myv = (lane < m) ? L[lane] : 0xFFFFFFFFu;
    int c = 0;
    #pragma unroll
    for (int j = 0; j < 32; j++) {
        unsigned o = __shfl_sync(~0u, myv, j);
        c += (o < myv) || (o == myv && j < lane);
    }
    bool hit = (c == rank) && (lane < m);
    unsigned bal = __ballot_sync(~0u, hit);
    int src = __ffs(bal) - 1;
    return __shfl_sync(~0u, myv, src);
}

__device__ __forceinline__ unsigned solve_list(unsigned* L, int m, int rank,
                                               unsigned tp, int sh0, int lane)
{
    int sh = sh0, m_ = m, r = rank; unsigned tp_ = tp;
    while (m_ > 32 && sh >= 0) {
        unsigned d = list_pass(L, m_, r, sh, lane);
        tp_ |= d << sh; sh -= 4;
    }
    return (m_ > 32) ? tp_ : final32(L, m_, r, lane);
}

__device__ __forceinline__ unsigned solve_list_smart(unsigned* L, int m, int rank,
                                                     unsigned umin, unsigned umax, int lane)
{
    if (umin == umax) return umin;
    int bit = 31 - __clz(umin ^ umax);
    int sh0 = (bit >> 2) << 2;
    unsigned pref = (sh0 >= 28) ? 0u : (umin & (~0u << (sh0 + 4)));
    return solve_list(L, m, rank, pref, sh0, lane);
}

// ---------------------------------------------------------------------------
// Kernel 1b: exact 819th-smallest of bias (one warp) -> g_t0 window center
// ---------------------------------------------------------------------------
__global__ void t0_kernel(const float* __restrict__ bias)
{
    __shared__ unsigned sk[NC];
    const int lane = threadIdx.x & 31;
    for (int i = lane; i < NC; i += 32) sk[i] = f2u(bias[i]);
    __syncwarp();
    unsigned ans;
    {
        int m = NC, r = KSEL, sh = 28; unsigned tp = 0;
        while (m > 32 && sh >= 0) {
            unsigned d = list_pass(sk, m, r, sh, lane);
            tp |= d << sh; sh -= 4;
        }
        ans = (m > 32) ? tp : final32(sk, m, r, lane);
    }
    if (lane == 0) g_t0 = u2f(ans);
}

// ---------------------------------------------------------------------------
// Kernel 2: windowed select around g_t0 (1 position/warp).
// ---------------------------------------------------------------------------
#define SEL_SMEM (2048 * 4 + 4 * 2 * SEL_CAP * 4)

__global__ void __launch_bounds__(128) select_kernel(const float* __restrict__ bias)
{
    extern __shared__ float smem[];
    float* sbias = smem;                          // 2048 floats
    unsigned* slist = (unsigned*)(smem + 2048);   // 4 warps * 2 * SEL_CAP

    const int tid = threadIdx.x;
    const int wid = tid >> 5, lane = tid & 31;

    {
        const float4* bsrc = (const float4*)bias;
        float4* bdst = (float4*)sbias;
        #pragma unroll
        for (int i = 0; i < 4; i++) bdst[tid + 128 * i] = bsrc[tid + 128 * i];
    }
    __syncthreads();

    const int pos = blockIdx.x * 4 + wid;
    const float4* vsrc = (const float4*)(g_conv + (size_t)pos * NC);
    unsigned* l1 = slist + wid * 2 * SEL_CAP;
    unsigned* l2 = l1 + SEL_CAP;

    const float t0 = g_t0;
    const float wlo = t0 - WIN, whi = t0 + WIN;
    const unsigned lt = (1u << lane) - 1u;

    int cb1 = 0, cb2 = 0;
    int n1 = 0, n2 = 0;
    unsigned mn1 = 0xFFFFFFFFu, mx1 = 0u, mn2 = 0xFFFFFFFFu, mx2 = 0u;
    {
        const float4* bs4 = (const float4*)sbias;
        #pragma unroll 1
        for (int half = 0; half < 2; half++) {
            float4 vv[8], bv[8];
            #pragma unroll
            for (int t = 0; t < 8; t++) {
                vv[t] = __ldg(vsrc + (half * 8 + t) * 32 + lane);
                bv[t] = bs4[(half * 8 + t) * 32 + lane];
            }
            #pragma unroll
            for (int t = 0; t < 8; t++) {
                #pragma unroll
                for (int e = 0; e < 4; e++) {
                    float v = (&vv[t].x)[e], bb = (&bv[t].x)[e];
                    float k1 = bb - v, k2 = bb + v;
                    bool below1 = k1 < wlo;
                    bool in1 = !below1 && (k1 < whi);
                    bool below2 = k2 < wlo;
                    bool in2 = !below2 && (k2 < whi);
                    cb1 += below1;
                    cb2 += below2;
                    unsigned bi1 = __ballot_sync(~0u, in1);
                    if (in1) {
                        unsigned u1 = f2u(k1);
                        mn1 = min(mn1, u1); mx1 = max(mx1, u1);
                        int ix = n1 + __popc(bi1 & lt); if (ix < SEL_CAP) l1[ix] = u1;
                    }
                    n1 += __popc(bi1);
                    unsigned bi2 = __ballot_sync(~0u, in2);
                    if (in2) {
                        unsigned u2 = f2u(k2);
                        mn2 = min(mn2, u2); mx2 = max(mx2, u2);
                        int ix = n2 + __popc(bi2 & lt); if (ix < SEL_CAP) l2[ix] = u2;
                    }
                    n2 += __popc(bi2);
                }
            }
        }
    }
    int tb1 = wsum(cb1), tb2 = wsum(cb2);
    int r1 = KSEL - tb1, r2 = KSEL - tb2;
    bool ok1 = (r1 >= 0) && (r1 < n1) && (n1 <= SEL_CAP);
    bool ok2 = (r2 >= 0) && (r2 < n2) && (n2 <= SEL_CAP);

    unsigned ansu1, ansu2;
    if (ok1 && ok2) {
        mn1 = wminu(mn1); mx1 = wmaxu(mx1);
        mn2 = wminu(mn2); mx2 = wmaxu(mx2);
        ansu1 = solve_list_smart(l1, n1, r1, mn1, mx1, lane);
        ansu2 = solve_list_smart(l2, n2, r2, mn2, mx2, lane);
    } else {
        int rank1 = KSEL, rank2 = KSEL;
        unsigned top1 = 0, top2 = 0, maskTop = 0;
        int m1 = NC, m2 = NC;
        int shift = 28;
        unsigned dig1, dig2;
        {
            int cnt = hist_sweep<false>(vsrc, sbias, 0, 0, 0, shift, lane);
            pick_bins(cnt, rank1, rank2, dig1, dig2, m1, m2, lane);
            top1 |= dig1 << shift; top2 |= dig2 << shift;
            maskTop |= 0xFu << shift; shift -= 4;
        }
        while ((m1 > SEL_CAP || m2 > SEL_CAP) && shift >= 0) {
            int cnt = hist_sweep<true>(vsrc, sbias, top1, top2, maskTop, shift, lane);
            pick_bins(cnt, rank1, rank2, dig1, dig2, m1, m2, lane);
            top1 |= dig1 << shift; top2 |= dig2 << shift;
            maskTop |= 0xFu << shift; shift -= 4;
        }
        bool en1 = (m1 <= SEL_CAP), en2 = (m2 <= SEL_CAP);
        compact_sweep(vsrc, sbias, top1, top2, maskTop, l1, l2, en1, en2, lane);
        ansu1 = en1 ? solve_list(l1, m1, rank1, top1, shift, lane) : top1;
        ansu2 = en2 ? solve_list(l2, m2, rank2, top2, shift, lane) : top2;
    }

    if (lane == 0) {
        g_t1[pos] = u2f(ansu1);
        g_t2[pos] = u2f(ansu2);
    }
}

// ---------------------------------------------------------------------------
// Kernel 3: masks + pooling. Sparse A + cp.async triple-buffered pipeline.
// ---------------------------------------------------------------------------
__device__ __forceinline__ unsigned smem_u32(const void* p) {
    unsigned a;
    asm("{ .reg .u64 t; cvta.to.shared.u64 t, %1; cvt.u32.u64 %0, t; }" : "=r"(a) : "l"(p));
    return a;
}

__global__ void __launch_bounds__(128) pool_kernel(const float* __restrict__ bias,
                                                   float* __restrict__ out)
{
    __shared__ float st1[NPOS9], st2[NPOS9];
    __shared__ float sA[6][28];
    __shared__ float4 s4[3][27 * 32];   // triple-buffered h-row slabs

    const int b = blockIdx.y;
    const int c0 = blockIdx.x * 128;
    const int tid = threadIdx.x;
    const int c = c0 + tid;

    for (int i = tid; i < NPOS9; i += 128) {
        st1[i] = g_t1[b * NPOS9 + i];
        st2[i] = g_t2[b * NPOS9 + i];
    }
    if (tid < 27) {
        int wcol = tid;
        const int sidx[6] = {0, 1, 3, 4, 6, 7};
        #pragma unroll
        for (int i = 0; i < 6; i++) {
            float a = 0.0f;
            #pragma unroll
            for (int q = 0; q < 2; q++) {
                int p = sidx[i] + q;
                int st = 3 * p, en = (st + 5 < 27) ? st + 5 : 27;
                if (wcol >= st && wcol < en) a += 0.5f / (float)(en - st);
            }
            sA[i][wcol] = a;
        }
    }

    const float bc = bias[c];
    const float* base = g_conv + ((size_t)(b * NPOS9)) * NC + c0;

    auto stage = [&](int h, int buf) {
        const float* rowbase = base + (size_t)(h * 27) * NC;
        unsigned sdst = smem_u32(&s4[buf][0]);
        #pragma unroll
        for (int k = 0; k < 7; k++) {
            int j = tid + 128 * k;
            if (j < 864) {
                int p = j >> 5, cq = j & 31;
                const float4* gp = (const float4*)(rowbase + (size_t)p * NC) + cq;
                asm volatile("cp.async.cg.shared.global [%0], [%1], 16;"
                             :: "r"(sdst + j * 16), "l"(gp));
            }
        }
        asm volatile("cp.async.commit_group;");
    };

    float acc1[36], acc2[36];
    #pragma unroll
    for (int k = 0; k < 36; k++) { acc1[k] = 0.0f; acc2[k] = 0.0f; }

    constexpr int PJ0[27] = {0,0,0,0,0,0,0,0,1,1,1,2,2,2,2,2,2,3,3,3,4,4,4,4,4,4,5};
    constexpr int PJ1[27] = {-1,-1,-1,1,1,1,1,1,-1,2,2,-1,3,3,3,3,3,-1,4,4,-1,5,5,5,5,5,-1};

    stage(0, 0);
    stage(1, 1);

    int buf = 0;
    #pragma unroll 1
    for (int h = 0; h < 27; h++) {
        if (h < 25) asm volatile("cp.async.wait_group 1;");
        else        asm volatile("cp.async.wait_group 0;");
        __syncthreads();
        if (h + 2 < 27) {
            int nb = buf + 2; if (nb >= 3) nb -= 3;
            stage(h + 2, nb);
        }

        const float* srow = (const float*)&s4[buf][0];
        float r1[6], r2[6];
        #pragma unroll
        for (int j = 0; j < 6; j++) { r1[j] = 0.0f; r2[j] = 0.0f; }
        const int hbase = h * 27;
        #pragma unroll
        for (int w = 0; w < 27; w++) {
            float v = srow[w * 128 + tid];
            float m1 = (bc - v < st1[hbase + w]) ? 1.0f : 0.0f;
            float m2 = (bc + v < st2[hbase + w]) ? 1.0f : 0.0f;
            {
                const int j = PJ0[w];
                float a = sA[j][w];
                r1[j] += a * m1;
                r2[j] += a * m2;
            }
            if (PJ1[w] >= 0) {
                const int j = PJ1[w];
                float a = sA[j][w];
                r1[j] += a * m1;
                r2[j] += a * m2;
            }
        }
        #pragma unroll
        for (int i = 0; i < 6; i++) {
            float ah = sA[i][h];
            if (ah != 0.0f) {
                #pragma unroll
                for (int j = 0; j < 6; j++) {
                    acc1[i * 6 + j] += ah * r1[j];
                    acc2[i * 6 + j] += ah * r2[j];
                }
            }
        }
        buf++; if (buf >= 3) buf = 0;
    }

    float* o1 = out + ((size_t)(b * NC + c)) * 36;
    float* o2 = o1 + (size_t)NB * NC * 36;
    #pragma unroll
    for (int k = 0; k < 36; k++) { o1[k] = acc1[k]; o2[k] = acc2[k]; }
}

// ---------------------------------------------------------------------------
extern "C" void kernel_launch(void* const* d_in, const int* in_sizes, int n_in,
                              void* d_out, int out_size)
{
    const float* x    = (const float*)d_in[0]; // [64,3,32,32]
    const float* w    = (const float*)d_in[1]; // [2048,3,6,6]
    const float* bias = (const float*)d_in[2]; // [2048]
    float* out = (float*)d_out;                // [2][64,2048,6,6]

    cudaFuncSetAttribute(conv_kernel, cudaFuncAttributeMaxDynamicSharedMemorySize, CONV_SMEM);
    cudaFuncSetAttribute(select_kernel, cudaFuncAttributeMaxDynamicSharedMemorySize, SEL_SMEM);

    conv_kernel<<<dim3(16, 64), 256, CONV_SMEM>>>(x, w);
    t0_kernel<<<1, 32>>>(bias);
    select_kernel<<<TOTPOS / 4, 128, SEL_SMEM>>>(bias);
    pool_kernel<<<dim3(16, 64), 128>>>(bias, out);
}